// round 3
// baseline (speedup 1.0000x reference)
#include <cuda_runtime.h>
#include <math.h>
#include <stdint.h>

// ---------------- problem constants ----------------
constexpr int B  = 2;
constexpr int C  = 32;
constexpr int NS = 32;
constexpr int NZ = 96;
constexpr int NX = 96;
constexpr int P  = NS * NZ * NX;      // 294912 per (b,c)
constexpr int NPT = B * P;            // 589824 spatial points
constexpr int M1 = 8, M2 = 12, M3 = 12;
constexpr int KS = 16, KZ = 24, KX = 12;   // kept modes per axis
constexpr float SLOPE = 0.1f;
constexpr float INV2DX = 50.0f;            // 0.5/0.01

// ---------------- scratch (device globals; no allocation) ----------------
__device__ float  g_hA[B * C * P];
__device__ float  g_hB[B * C * P];
__device__ float  g_h1[B * C * P];
__device__ float2 g_S1[B * C * NS * NZ * KX];   // 2,359,296
__device__ float2 g_S2[B * C * NS * KZ * KX];   //   589,824
__device__ float2 g_S3[B * C * KS * KZ * KX];   //   294,912
__device__ float2 g_G [B * C * KS * KZ * KX];
__device__ float2 g_T1[B * C * NS * KZ * KX];
__device__ float2 g_T2[B * C * NS * NZ * KX];
__device__ float  g_t0dx[NPT];
__device__ float  g_t0dz[NPT];
__device__ double g_sum[C];
__device__ double g_sq[C];
__device__ float  g_scale[C];
__device__ float  g_shift[C];

// twiddles (normalization folded into forward tables)
__device__ float2 g_twFx[KX * NX];
__device__ float2 g_twFz[KZ * NZ];
__device__ float2 g_twFs[KS * NS];
__device__ float2 g_twIs[NS * KS];
__device__ float2 g_twIz[NZ * KZ];
__device__ float2 g_twIx[NX * KX];

__device__ __forceinline__ float lrelu(float v) { return v > 0.f ? v : SLOPE * v; }
__device__ __forceinline__ float* hbuf(int s) { return s ? g_hB : g_hA; }

// ---------------- twiddle init ----------------
__global__ void k_init_tw() {
    int t = blockIdx.x * blockDim.x + threadIdx.x;
    int stride = gridDim.x * blockDim.x;
    for (int i = t; i < KX * NX; i += stride) {
        int k = i / NX, x = i % NX;
        double f = 2.0 * double((k * x) % NX) / NX;
        double s, c; sincospi(f, &s, &c);
        g_twFx[i] = make_float2((float)(c / NX), (float)(-s / NX));
        // inverse x: layout [x][k]
        g_twIx[x * KX + k] = make_float2((float)c, (float)s);
    }
    for (int i = t; i < KZ * NZ; i += stride) {
        int ki = i / NZ, z = i % NZ;
        int kz = (ki < M2) ? ki : ki + (NZ - KZ);   // ki-12 -> kz 84..95
        double f = 2.0 * double((kz * z) % NZ) / NZ;
        double s, c; sincospi(f, &s, &c);
        g_twFz[i] = make_float2((float)(c / NZ), (float)(-s / NZ));
        g_twIz[z * KZ + ki] = make_float2((float)c, (float)s);
    }
    for (int i = t; i < KS * NS; i += stride) {
        int ki = i / NS, s0 = i % NS;
        int ks = (ki < M1) ? ki : ki + (NS - KS);   // ki-8 -> ks 24..31
        double f = 2.0 * double((ks * s0) % NS) / NS;
        double s, c; sincospi(f, &s, &c);
        g_twFs[i] = make_float2((float)(c / NS), (float)(-s / NS));
        g_twIs[s0 * KS + ki] = make_float2((float)c, (float)s);
    }
}

// ---------------- fc0 + T0 derivatives ----------------
__global__ void k_fc0t0(const float* __restrict__ x, const float* __restrict__ w,
                        const float* __restrict__ bb) {
    int p = blockIdx.x * blockDim.x + threadIdx.x;
    if (p >= NPT) return;
    int b = p / P, p0 = p % P;
    int xx = p0 % NX;
    int z  = (p0 / NX) % NZ;
    float a0 = x[2 * p], a1 = x[2 * p + 1];
#pragma unroll
    for (int c = 0; c < C; c++)
        g_hA[(b * C + c) * P + p0] = a0 * w[c] + a1 * w[C + c] + bb[c];
    float xm = (xx > 0)      ? x[2 * (p - 1) + 1]  : 0.f;
    float xp = (xx < NX - 1) ? x[2 * (p + 1) + 1]  : 0.f;
    g_t0dx[p] = (xp - xm) * INV2DX;
    float zm = (z > 0)       ? x[2 * (p - NX) + 1] : 0.f;
    float zp = (z < NZ - 1)  ? x[2 * (p + NX) + 1] : 0.f;
    g_t0dz[p] = (zp - zm) * INV2DX;
}

// ---------------- forward DFT stages ----------------
__global__ void k_f1(int sel) {           // x axis: real 96 -> 12 modes
    int g = blockIdx.x * blockDim.x + threadIdx.x;   // line*12 + kx
    int line = g / KX, k = g % KX;
    const float* src = hbuf(sel) + line * NX;
    const float2* tw = g_twFx + k * NX;
    float re = 0.f, im = 0.f;
#pragma unroll 8
    for (int x = 0; x < NX; x++) {
        float v = src[x]; float2 t = tw[x];
        re += v * t.x; im += v * t.y;
    }
    g_S1[g] = make_float2(re, im);
}

__global__ void k_f2() {                  // z axis: 96 -> 24 modes
    int g = blockIdx.x * blockDim.x + threadIdx.x;
    int kx = g % KX, kzi = (g / KX) % KZ, bcs = g / (KX * KZ);
    const float2* src = g_S1 + bcs * (NZ * KX) + kx;
    const float2* tw  = g_twFz + kzi * NZ;
    float re = 0.f, im = 0.f;
#pragma unroll 8
    for (int z = 0; z < NZ; z++) {
        float2 v = src[z * KX]; float2 t = tw[z];
        re += v.x * t.x - v.y * t.y;
        im += v.x * t.y + v.y * t.x;
    }
    g_S2[g] = make_float2(re, im);
}

__global__ void k_f3() {                  // s axis: 32 -> 16 modes
    int g = blockIdx.x * blockDim.x + threadIdx.x;
    int kx = g % KX, kzi = (g / KX) % KZ, ksi = (g / 288) % KS, bc = g / 4608;
    const float2* src = g_S2 + bc * NS * 288 + kzi * KX + kx;
    const float2* tw  = g_twFs + ksi * NS;
    float re = 0.f, im = 0.f;
#pragma unroll 8
    for (int s = 0; s < NS; s++) {
        float2 v = src[s * 288]; float2 t = tw[s];
        re += v.x * t.x - v.y * t.y;
        im += v.x * t.y + v.y * t.x;
    }
    g_S3[(bc * KS + ksi) * 288 + kzi * KX + kx] = make_float2(re, im);
}

// ---------------- spectral multiply ----------------
__global__ void k_mul(int L, const float* __restrict__ spec) {
    int g = blockIdx.x * blockDim.x + threadIdx.x;
    int kx = g % KX, kzi = (g / KX) % KZ, ksi = (g / 288) % KS;
    int co = (g / 4608) % C, b = g / (4608 * C);
    int corner = (ksi >= M1 ? 1 : 0) + (kzi >= M2 ? 2 : 0);
    int k1 = (ksi >= M1) ? ksi - M1 : ksi;
    int k2 = (kzi >= M2) ? kzi - M2 : kzi;
    // weight element ((((L*4+corner)*C + ci)*C + co)*M1+k1)*M2+k2)*M3+kx, *2
    int wbase = ((((L * 4 + corner) * C) * C + co) * M1 + k1) * M2 + k2;
    wbase = wbase * M3 + kx;
    const int wstride = C * M1 * M2 * M3;   // per ci step (in complex elems)
    const float2* xin = g_S3 + (b * C) * 4608 + ksi * 288 + kzi * KX + kx;
    float re = 0.f, im = 0.f;
#pragma unroll 8
    for (int ci = 0; ci < C; ci++) {
        float2 a = xin[ci * 4608];
        float wr = spec[2 * (wbase + ci * wstride)];
        float wi = spec[2 * (wbase + ci * wstride) + 1];
        re += a.x * wr - a.y * wi;
        im += a.x * wi + a.y * wr;
    }
    g_G[g] = make_float2(re, im);
}

// ---------------- inverse DFT stages ----------------
__global__ void k_i1() {                  // 16 -> 32 along s
    int g = blockIdx.x * blockDim.x + threadIdx.x;
    int kx = g % KX, kzi = (g / KX) % KZ, s = (g / 288) % NS, bc = g / (288 * NS);
    const float2* src = g_G + bc * 4608 + kzi * KX + kx;
    const float2* tw  = g_twIs + s * KS;
    float re = 0.f, im = 0.f;
#pragma unroll
    for (int k = 0; k < KS; k++) {
        float2 v = src[k * 288]; float2 t = tw[k];
        re += v.x * t.x - v.y * t.y;
        im += v.x * t.y + v.y * t.x;
    }
    g_T1[g] = make_float2(re, im);
}

__global__ void k_i2() {                  // 24 -> 96 along z
    int g = blockIdx.x * blockDim.x + threadIdx.x;
    int kx = g % KX, z = (g / KX) % NZ, s = (g / (KX * NZ)) % NS, bc = g / (KX * NZ * NS);
    const float2* src = g_T1 + (bc * NS + s) * 288 + kx;
    const float2* tw  = g_twIz + z * KZ;
    float re = 0.f, im = 0.f;
#pragma unroll
    for (int k = 0; k < KZ; k++) {
        float2 v = src[k * KX]; float2 t = tw[k];
        re += v.x * t.x - v.y * t.y;
        im += v.x * t.y + v.y * t.x;
    }
    g_T2[g] = make_float2(re, im);
}

__global__ void k_i3() {                  // 12 -> 96 along x, real part -> g_h1
    int line = blockIdx.x;                // (b,c,s,z)
    int x = threadIdx.x;                  // 0..95
    __shared__ float2 cf[KX];
    if (x < KX) cf[x] = g_T2[line * KX + x];
    __syncthreads();
    const float2* tw = g_twIx + x * KX;
    float acc = 0.f;
#pragma unroll
    for (int k = 0; k < KX; k++)
        acc += cf[k].x * tw[k].x - cf[k].y * tw[k].y;
    g_h1[line * NX + x] = acc;
}

// ---------------- pointwise conv (w path) + add into g_h1 ----------------
__global__ void k_w(int sel, int L, const float* __restrict__ ww,
                    const float* __restrict__ wb) {
    __shared__ float sW[C * C];
    for (int i = threadIdx.x; i < C * C; i += blockDim.x)
        sW[i] = ww[L * C * C + i];
    __syncthreads();
    int p = blockIdx.x * blockDim.x + threadIdx.x;
    if (p >= NPT) return;
    int b = p / P, p0 = p % P;
    const float* h = hbuf(sel) + b * C * P + p0;
    float acc[C];
#pragma unroll
    for (int co = 0; co < C; co++) acc[co] = wb[L * C + co];
    for (int ci = 0; ci < C; ci++) {
        float v = h[ci * P];
#pragma unroll
        for (int co = 0; co < C; co++) acc[co] += sW[co * C + ci] * v;
    }
    float* o = g_h1 + b * C * P + p0;
#pragma unroll
    for (int co = 0; co < C; co++) o[co * P] += acc[co];
}

// ---------------- batchnorm ----------------
__global__ void k_zero() {
    if (threadIdx.x < C) { g_sum[threadIdx.x] = 0.0; g_sq[threadIdx.x] = 0.0; }
}

__global__ void k_stat() {
    int bid = blockIdx.x;
    int c = (bid / (P / 1024)) % C;
    const float* src = g_h1 + (size_t)bid * 1024;
    float s = 0.f, q = 0.f;
    for (int i = threadIdx.x; i < 1024; i += blockDim.x) {
        float v = src[i]; s += v; q += v * v;
    }
#pragma unroll
    for (int o = 16; o; o >>= 1) {
        s += __shfl_down_sync(0xffffffffu, s, o);
        q += __shfl_down_sync(0xffffffffu, q, o);
    }
    __shared__ float ws[8], wq[8];
    int wid = threadIdx.x >> 5, lane = threadIdx.x & 31;
    if (lane == 0) { ws[wid] = s; wq[wid] = q; }
    __syncthreads();
    if (threadIdx.x == 0) {
        float S = 0.f, Q = 0.f;
        int nw = blockDim.x >> 5;
        for (int i = 0; i < nw; i++) { S += ws[i]; Q += wq[i]; }
        atomicAdd(&g_sum[c], (double)S);
        atomicAdd(&g_sq[c],  (double)Q);
    }
}

__global__ void k_fin(int L, const float* __restrict__ bg, const float* __restrict__ bb) {
    int c = threadIdx.x;
    if (c < C) {
        double n = (double)NPT;
        double m = g_sum[c] / n;
        double var = g_sq[c] / n - m * m;
        float sc = bg[L * C + c] * (float)(1.0 / sqrt(var + 1e-5));
        g_scale[c] = sc;
        g_shift[c] = bb[L * C + c] - (float)m * sc;
    }
}

__global__ void k_bnapply(int outsel) {
    int idx = blockIdx.x * blockDim.x + threadIdx.x;
    int c = (idx / P) % C;
    float v = g_h1[idx] * g_scale[c] + g_shift[c];
    hbuf(outsel)[idx] = lrelu(v);
}

// ---------------- fused MLP + mask ----------------
constexpr int OW1 = 0,      OB1 = 4096;
constexpr int OW2 = 4224,   OB2 = 12416;
constexpr int OW3 = 12480,  OB3 = 14528;
constexpr int OW4 = 14560,  OB4 = 16608;
constexpr int OW5 = 16672,  OB5 = 24864;
constexpr int OW7 = 24992,  OB7 = 25120;
constexpr int SM_FLOATS = 25121;
constexpr int SMEM_MLP = SM_FLOATS * 4;

__global__ void __launch_bounds__(256, 1) k_mlp(
    const float* __restrict__ x,
    const float* __restrict__ w1, const float* __restrict__ b1,
    const float* __restrict__ w2, const float* __restrict__ b2,
    const float* __restrict__ w3, const float* __restrict__ b3,
    const float* __restrict__ w4, const float* __restrict__ b4,
    const float* __restrict__ w5, const float* __restrict__ b5,
    const float* __restrict__ w7, const float* __restrict__ b7,
    float* __restrict__ out) {
    extern __shared__ float sm[];
    int tid = threadIdx.x;
    for (int i = tid; i < 4096; i += 256) sm[OW1 + i] = w1[i];
    for (int i = tid; i < 128;  i += 256) sm[OB1 + i] = b1[i];
    for (int i = tid; i < 8192; i += 256) sm[OW2 + i] = w2[i];
    for (int i = tid; i < 64;   i += 256) sm[OB2 + i] = b2[i];
    for (int i = tid; i < 2048; i += 256) sm[OW3 + i] = w3[i];
    for (int i = tid; i < 32;   i += 256) sm[OB3 + i] = b3[i];
    for (int i = tid; i < 2048; i += 256) sm[OW4 + i] = w4[i];
    for (int i = tid; i < 64;   i += 256) sm[OB4 + i] = b4[i];
    for (int i = tid; i < 8192; i += 256) sm[OW5 + i] = w5[i];
    for (int i = tid; i < 128;  i += 256) sm[OB5 + i] = b5[i];
    for (int i = tid; i < 128;  i += 256) sm[OW7 + i] = w7[i];
    if (tid == 0) sm[OB7] = b7[0];
    __syncthreads();

    int p = blockIdx.x * blockDim.x + tid;
    int b = p / P, p0 = p % P;
    const float* h = g_hA + b * C * P + p0;   // final activations live in hA
    float in[32];
#pragma unroll
    for (int i = 0; i < 32; i++) in[i] = h[i * P];

    float a2[64];
#pragma unroll
    for (int k = 0; k < 64; k++) a2[k] = sm[OB2 + k];
#pragma unroll 1
    for (int j = 0; j < 128; j++) {
        float a = sm[OB1 + j];
#pragma unroll
        for (int i = 0; i < 32; i++) a += in[i] * sm[OW1 + i * 128 + j];
        a = lrelu(a);
#pragma unroll
        for (int k = 0; k < 64; k++) a2[k] += a * sm[OW2 + j * 64 + k];
    }
#pragma unroll
    for (int k = 0; k < 64; k++) a2[k] = lrelu(a2[k]);

    float a3[32];
#pragma unroll
    for (int k = 0; k < 32; k++) a3[k] = sm[OB3 + k];
#pragma unroll 1
    for (int j = 0; j < 64; j++) {
        float a = a2[j];
#pragma unroll
        for (int k = 0; k < 32; k++) a3[k] += a * sm[OW3 + j * 32 + k];
    }
#pragma unroll
    for (int k = 0; k < 32; k++) a3[k] = lrelu(a3[k]);

    float a4[64];
#pragma unroll
    for (int k = 0; k < 64; k++) a4[k] = sm[OB4 + k];
#pragma unroll 1
    for (int j = 0; j < 32; j++) {
        float a = a3[j];
#pragma unroll
        for (int k = 0; k < 64; k++) a4[k] += a * sm[OW4 + j * 64 + k];
    }
#pragma unroll
    for (int k = 0; k < 64; k++) a4[k] = lrelu(a4[k]);

    float tau = sm[OB7];
#pragma unroll 1
    for (int k = 0; k < 128; k++) {
        float a = sm[OB5 + k];
#pragma unroll
        for (int j = 0; j < 64; j++) a += a4[j] * sm[OW5 + j * 128 + k];
        a = lrelu(a);
        tau += a * sm[OW7 + k];
    }

    float T0 = x[2 * p + 1];
    int z = (p0 / NX) % NZ;
    float mask = (z < 2) ? 0.f : ((T0 < 0.01f) ? T0 : 1.f);
    out[p] = tau * mask;
}

// ---------------- loss ----------------
__global__ void k_loss(const float* __restrict__ y, float* __restrict__ out) {
    int p = blockIdx.x * blockDim.x + threadIdx.x;
    if (p >= NPT) return;
    int p0 = p % P;
    int xx = p0 % NX;
    int z = (p0 / NX) % NZ;
    const float* tau = out;
    float tm = (xx > 0)      ? tau[p - 1]  : 0.f;
    float tp = (xx < NX - 1) ? tau[p + 1]  : 0.f;
    float dx = (tp - tm) * INV2DX + g_t0dx[p];
    float zm = (z > 0)       ? tau[p - NX] : 0.f;
    float zp = (z < NZ - 1)  ? tau[p + NX] : 0.f;
    float dz = (zp - zm) * INV2DX + g_t0dz[p];
    out[NPT + p] = dx * dx + dz * dz - y[p];
}

// ---------------- launch ----------------
extern "C" void kernel_launch(void* const* d_in, const int* in_sizes, int n_in,
                              void* d_out, int out_size) {
    const float* x      = (const float*)d_in[0];
    const float* y      = (const float*)d_in[1];
    const float* fc0_w  = (const float*)d_in[2];
    const float* fc0_b  = (const float*)d_in[3];
    const float* spec_w = (const float*)d_in[4];
    const float* w_w    = (const float*)d_in[5];
    const float* w_b    = (const float*)d_in[6];
    const float* bn_g   = (const float*)d_in[7];
    const float* bn_b   = (const float*)d_in[8];
    const float* fc1_w  = (const float*)d_in[9];
    const float* fc1_b  = (const float*)d_in[10];
    const float* fc2_w  = (const float*)d_in[11];
    const float* fc2_b  = (const float*)d_in[12];
    const float* fc3_w  = (const float*)d_in[13];
    const float* fc3_b  = (const float*)d_in[14];
    const float* fc4_w  = (const float*)d_in[15];
    const float* fc4_b  = (const float*)d_in[16];
    const float* fc5_w  = (const float*)d_in[17];
    const float* fc5_b  = (const float*)d_in[18];
    const float* fc7_w  = (const float*)d_in[19];
    const float* fc7_b  = (const float*)d_in[20];
    float* out = (float*)d_out;

    cudaFuncSetAttribute(k_mlp, cudaFuncAttributeMaxDynamicSharedMemorySize, SMEM_MLP);

    k_init_tw<<<32, 256>>>();
    k_fc0t0<<<NPT / 256, 256>>>(x, fc0_w, fc0_b);

    for (int L = 0; L < 4; L++) {
        int sel = L & 1;          // input buffer: 0 -> hA, 1 -> hB
        k_f1<<<(B * C * NS * NZ * KX) / 256, 256>>>(sel);
        k_f2<<<(B * C * NS * KZ * KX) / 256, 256>>>();
        k_f3<<<(B * C * KS * KZ * KX) / 256, 256>>>();
        k_mul<<<(B * C * KS * KZ * KX) / 256, 256>>>(L, spec_w);
        k_i1<<<(B * C * NS * KZ * KX) / 256, 256>>>();
        k_i2<<<(B * C * NS * NZ * KX) / 256, 256>>>();
        k_i3<<<B * C * NS * NZ, 96>>>();
        k_w<<<(NPT + 255) / 256, 256>>>(sel, L, w_w, w_b);
        k_zero<<<1, 32>>>();
        k_stat<<<B * C * (P / 1024), 256>>>();
        k_fin<<<1, 32>>>(L, bn_g, bn_b);
        k_bnapply<<<(B * C * P) / 256, 256>>>(1 - sel);
    }

    k_mlp<<<NPT / 256, 256, SMEM_MLP>>>(x,
        fc1_w, fc1_b, fc2_w, fc2_b, fc3_w, fc3_b,
        fc4_w, fc4_b, fc5_w, fc5_b, fc7_w, fc7_b, out);
    k_loss<<<NPT / 256, 256>>>(y, out);
}